// round 17
// baseline (speedup 1.0000x reference)
#include <cuda_runtime.h>
#include <cuda_fp16.h>
#include <math.h>
#include <stdint.h>

#define BATCH 2
#define SEQ   4096
#define CHN   1280
#define HEADS 8
#define HDIM  160
#define BHN   16
#define MTOT  8192

// Scratch (allocation-free rule: __device__ globals), all fp16 operands
__device__ __half g_xh [(size_t)MTOT * CHN];     // [row][k]
__device__ __half g_aoh[(size_t)MTOT * CHN];     // [row][k]
__device__ __half g_wqh[(size_t)CHN * CHN];      // W^T: [n][k]
__device__ __half g_wkh[(size_t)CHN * CHN];
__device__ __half g_wvh[(size_t)CHN * CHN];
__device__ __half g_woh[(size_t)CHN * CHN];
__device__ __half g_qh [(size_t)BHN * SEQ * HDIM]; // [bh][s][d], pre-scaled
__device__ __half g_kh [(size_t)BHN * SEQ * HDIM]; // [bh][s][d]
__device__ __half g_vh [(size_t)BHN * HDIM * SEQ]; // [bh][d][s] (transposed)

// ---------------------------------------------------------------------------
// helpers
// ---------------------------------------------------------------------------
__device__ __forceinline__ uint32_t f2h2(float lo, float hi) {
    __half2 h = __floats2half2_rn(lo, hi);
    return *reinterpret_cast<uint32_t*>(&h);
}

// D(16x8 f32) += A(16x16 f16) * B(16x8 f16)
__device__ __forceinline__ void mmaf16(float* c, const uint32_t* a, const uint32_t* b) {
    asm volatile(
        "mma.sync.aligned.m16n8k16.row.col.f32.f16.f16.f32 "
        "{%0,%1,%2,%3}, {%4,%5,%6,%7}, {%8,%9}, {%0,%1,%2,%3};\n"
        : "+f"(c[0]), "+f"(c[1]), "+f"(c[2]), "+f"(c[3])
        : "r"(a[0]), "r"(a[1]), "r"(a[2]), "r"(a[3]), "r"(b[0]), "r"(b[1]));
}

__device__ __forceinline__ void ldsm4(uint32_t* r, uint32_t addr) {
    asm volatile("ldmatrix.sync.aligned.m8n8.x4.shared.b16 {%0,%1,%2,%3}, [%4];"
                 : "=r"(r[0]), "=r"(r[1]), "=r"(r[2]), "=r"(r[3]) : "r"(addr));
}

// x4 covering TWO n-tiles (8 rows each) x k16: lanes 0-7 -> n-rows@k0,
// 8-15 -> n-rows@k8, 16-23 -> n+8 rows@k0, 24-31 -> n+8 rows@k8.
// Returns r[0],r[1] = frag for tile n; r[2],r[3] = frag for tile n+8.
__device__ __forceinline__ void ldsm4_b2(uint32_t* r, uint32_t base,
                                         int row0, int stride_b, int koff_b,
                                         int lane) {
    int m = lane >> 3, wi = lane & 7;
    int row = row0 + (m >> 1) * 8 + wi;
    ldsm4(r, base + (uint32_t)(row * stride_b + koff_b + (m & 1) * 16));
}

__device__ __forceinline__ void cp16(uint32_t dst, const void* src) {
    asm volatile("cp.async.cg.shared.global [%0], [%1], 16;\n" :: "r"(dst), "l"(src));
}
__device__ __forceinline__ void cp_commit() { asm volatile("cp.async.commit_group;\n"); }
__device__ __forceinline__ void cp_wait0() {
    asm volatile("cp.async.wait_group 0;\n" ::: "memory");
}
template <int N> __device__ __forceinline__ void cp_waitn() {
    asm volatile("cp.async.wait_group %0;\n" :: "n"(N) : "memory");
}

// exp(x) for x <= 0 on the FMA pipe (no MUFU). |rel err| ~ 2.4e-6.
__device__ __forceinline__ float fast_exp(float x) {
    x = fmaxf(x, -80.0f);
    float y = x * 1.4426950408889634f;
    float t = y + 12582912.0f;
    int   e = __float_as_int(t);
    float n = t - 12582912.0f;
    float f = y - n;
    float p = 1.3333558e-3f;
    p = fmaf(p, f, 9.6181291e-3f);
    p = fmaf(p, f, 5.5504109e-2f);
    p = fmaf(p, f, 2.4022651e-1f);
    p = fmaf(p, f, 6.9314718e-1f);
    p = fmaf(p, f, 1.0f);
    return __int_as_float(__float_as_int(p) + (e << 23));
}

// ---------------------------------------------------------------------------
// Kernel 0: round X + weights to fp16. X row-major; W stored transposed [n][k].
// ---------------------------------------------------------------------------
__global__ __launch_bounds__(256) void cvt_all(
    const float* __restrict__ X,  const float* __restrict__ Wq,
    const float* __restrict__ Wk, const float* __restrict__ Wv,
    const float* __restrict__ Wo)
{
    const int NX = MTOT * CHN / 4;
    const int NW = CHN * CHN / 4;
    int i = blockIdx.x * 256 + threadIdx.x;
    if (i < NX) {
        int base = i * 4;
        int row = base / CHN, c = base - row * CHN;
        float4 v = *(const float4*)&X[(size_t)row * CHN + c];
        uint2 u = make_uint2(f2h2(v.x, v.y), f2h2(v.z, v.w));
        *(uint2*)&g_xh[(size_t)row * CHN + c] = u;
        return;
    }
    i -= NX;
    if (i >= 4 * NW) return;
    const float* s; __half* d2;
    if (i < NW)          { s = Wq; d2 = g_wqh; }
    else if (i < 2 * NW) { s = Wk; d2 = g_wkh; i -= NW; }
    else if (i < 3 * NW) { s = Wv; d2 = g_wvh; i -= 2 * NW; }
    else                 { s = Wo; d2 = g_woh; i -= 3 * NW; }
    int base = i * 4;
    int k = base / CHN, n = base - k * CHN;
    float4 v = *(const float4*)&s[(size_t)k * CHN + n];
    d2[(size_t)(n + 0) * CHN + k] = __float2half_rn(v.x);
    d2[(size_t)(n + 1) * CHN + k] = __float2half_rn(v.y);
    d2[(size_t)(n + 2) * CHN + k] = __float2half_rn(v.z);
    d2[(size_t)(n + 3) * CHN + k] = __float2half_rn(v.w);
}

// ---------------------------------------------------------------------------
// fp16 GEMM core: CTA 128x128, 8 warps (2m x 4n), warp 64x32, k-chunks of 32.
// 3-stage cp.async pipeline (2 groups in flight, wait_group 1).
// smem: As 3 x 10240B at 0, Bs 3 x 10240B at 30720. Total 61440B dynamic.
// ---------------------------------------------------------------------------
#define GEMM_SMEM 61440

__device__ __forceinline__ void hgemm_core(
    const __half* __restrict__ A, const __half* __restrict__ B,
    int row0, int col0, float c[16][4], uint32_t smem_u)
{
    uint32_t As_u = smem_u;
    uint32_t Bs_u = smem_u + 30720u;

    const int tid = threadIdx.x;
    const int warp = tid >> 5, lane = tid & 31;
    const int wm = warp >> 2, wn = warp & 3;

    auto issue = [&](int kb, int buf) {
#pragma unroll
        for (int it = 0; it < 2; it++) {
            int lin = it * 256 + tid;             // 512: 128 rows x 4 segs
            int row = lin >> 2, seg = lin & 3;
            cp16(As_u + (uint32_t)(buf * 10240 + row * 80 + seg * 16),
                 &A[(size_t)(row0 + row) * CHN + kb + seg * 8]);
            cp16(Bs_u + (uint32_t)(buf * 10240 + row * 80 + seg * 16),
                 &B[(size_t)(col0 + row) * CHN + kb + seg * 8]);
        }
        cp_commit();
    };

    issue(0, 0);
    issue(32, 1);

    for (int ic = 0; ic < 40; ic++) {
        const int buf = ic % 3;
        cp_waitn<1>();
        __syncthreads();
        if (ic + 2 < 40) issue((ic + 2) * 32, (ic + 2) % 3);
#pragma unroll
        for (int ks = 0; ks < 2; ks++) {
            uint32_t af[4][4], bf[2][4];
#pragma unroll
            for (int mt = 0; mt < 4; mt++)
                ldsm4(af[mt], As_u + (uint32_t)(buf * 10240 +
                      (wm * 64 + mt * 16 + (lane & 15)) * 80 +
                      ks * 32 + (lane >> 4) * 16));
#pragma unroll
            for (int np = 0; np < 2; np++)
                ldsm4_b2(bf[np], Bs_u + (uint32_t)(buf * 10240),
                         wn * 32 + np * 16, 80, ks * 32, lane);
#pragma unroll
            for (int mt = 0; mt < 4; mt++)
#pragma unroll
                for (int nt = 0; nt < 4; nt++)
                    mmaf16(c[mt * 4 + nt], af[mt], bf[nt >> 1] + (nt & 1) * 2);
        }
    }
}

// ---------------------------------------------------------------------------
// Kernel 1: fused QKV projection (fp16 HMMA); epilogues write attn layouts.
// ---------------------------------------------------------------------------
__global__ __launch_bounds__(256, 2) void qkv_h()
{
    extern __shared__ __half smem_g[];
    uint32_t smem_u = (uint32_t)__cvta_generic_to_shared(smem_g);
    float c[16][4];
#pragma unroll
    for (int i = 0; i < 16; i++)
#pragma unroll
        for (int j = 0; j < 4; j++) c[i][j] = 0.f;

    const __half* __restrict__ W =
        (blockIdx.z == 0) ? g_wqh : (blockIdx.z == 1 ? g_wkh : g_wvh);
    hgemm_core(g_xh, W, blockIdx.y * 128, blockIdx.x * 128, c, smem_u);

    const int lane = threadIdx.x & 31, warp = threadIdx.x >> 5;
    const int g = lane >> 2, t = lane & 3;
    const int wm = warp >> 2, wn = warp & 3;
    const float scale = 0.07905694150420949f;  // 1/sqrt(160)

#pragma unroll
    for (int mt = 0; mt < 4; mt++) {
#pragma unroll
        for (int nt = 0; nt < 4; nt++) {
            int r = blockIdx.y * 128 + wm * 64 + mt * 16 + g;
            int col = blockIdx.x * 128 + wn * 32 + nt * 8 + 2 * t;
            int h = col / HDIM, d = col - h * HDIM;
            float* cc = c[mt * 4 + nt];
            if (blockIdx.z == 0) {
#pragma unroll
                for (int hf = 0; hf < 2; hf++) {
                    int row = r + hf * 8;
                    int b = row >> 12, s = row & (SEQ - 1);
                    size_t o = ((size_t)(b * HEADS + h) * SEQ + s) * HDIM + d;
                    *(uint32_t*)&g_qh[o] = f2h2(cc[hf * 2] * scale, cc[hf * 2 + 1] * scale);
                }
            } else if (blockIdx.z == 1) {
#pragma unroll
                for (int hf = 0; hf < 2; hf++) {
                    int row = r + hf * 8;
                    int b = row >> 12, s = row & (SEQ - 1);
                    size_t o = ((size_t)(b * HEADS + h) * SEQ + s) * HDIM + d;
                    *(uint32_t*)&g_kh[o] = f2h2(cc[hf * 2], cc[hf * 2 + 1]);
                }
            } else {
#pragma unroll
                for (int i = 0; i < 4; i++) {
                    int row = r + (i >> 1) * 8;
                    int b = row >> 12, s = row & (SEQ - 1);
                    g_vh[((size_t)(b * HEADS + h) * HDIM + d + (i & 1)) * SEQ + s] =
                        __float2half_rn(cc[i]);
                }
            }
        }
    }
}

// ---------------------------------------------------------------------------
// Kernel 2: flash attention, fp16 HMMA. CTA: 128 q rows, 8 warps x 16 q rows.
// KV tile = 32 keys; warp-local softmax; P: S-regs -> A-frags directly.
// 3-stage pipeline: sK 3 x 10752B at 0, sV 3 x 12800B at 32256. 70656B dyn.
// ---------------------------------------------------------------------------
#define ATTN_SMEM 70656

__global__ __launch_bounds__(256, 2) void attn_h()
{
    extern __shared__ __half smem_a[];
    uint32_t sK_u = (uint32_t)__cvta_generic_to_shared(smem_a);
    uint32_t sV_u = sK_u + 32256u;

    const int bh = blockIdx.y;
    const int q0 = blockIdx.x * 128;
    const int tid = threadIdx.x, w = tid >> 5, lane = tid & 31;
    const int g = lane >> 2, t = lane & 3;
    const int r0 = q0 + w * 16 + g;

    // ---- Q fragments straight from gmem (pre-scaled fp16) ----
    uint32_t qa[10][4];
    {
        const __half* Qb = &g_qh[((size_t)bh * SEQ + r0) * HDIM];
#pragma unroll
        for (int ks = 0; ks < 10; ks++) {
            qa[ks][0] = *(const uint32_t*)(Qb + ks * 16 + 2 * t);
            qa[ks][1] = *(const uint32_t*)(Qb + 8 * HDIM + ks * 16 + 2 * t);
            qa[ks][2] = *(const uint32_t*)(Qb + ks * 16 + 8 + 2 * t);
            qa[ks][3] = *(const uint32_t*)(Qb + 8 * HDIM + ks * 16 + 8 + 2 * t);
        }
    }

    const __half* __restrict__ Kg = &g_kh[(size_t)bh * SEQ * HDIM];
    const __half* __restrict__ Vg = &g_vh[(size_t)bh * HDIM * SEQ];

    auto issue = [&](int kt, int buf) {
#pragma unroll
        for (int it = 0; it < 5; it++) {
            int lin = it * 256 + tid;            // 1280 cp16 total
            if (lin < 640) {                     // K: 32 rows x 20 segs
                int row = lin / 20, seg = lin - row * 20;
                cp16(sK_u + (uint32_t)(buf * 10752 + row * 336 + seg * 16),
                     Kg + (size_t)(kt + row) * HDIM + seg * 8);
            } else {                             // V: 160 rows x 4 segs
                int v = lin - 640;
                int d = v >> 2, seg = v & 3;
                cp16(sV_u + (uint32_t)(buf * 12800 + d * 80 + seg * 16),
                     Vg + (size_t)d * SEQ + kt + seg * 8);
            }
        }
        cp_commit();
    };
    issue(0, 0);
    issue(32, 1);

    float o[20][4];
#pragma unroll
    for (int nt = 0; nt < 20; nt++)
#pragma unroll
        for (int j = 0; j < 4; j++) o[nt][j] = 0.f;
    float m0 = -1e30f, m1 = -1e30f, l0 = 0.f, l1 = 0.f;

    for (int it = 0; it < 128; it++) {
        const int buf = it % 3;
        cp_waitn<1>();
        __syncthreads();
        if (it + 2 < 128) issue((it + 2) * 32, (it + 2) % 3);

        // ---- S = Q @ K^T (16q x 32k per warp, full tile width) ----
        float s[4][4];
#pragma unroll
        for (int nt = 0; nt < 4; nt++)
#pragma unroll
            for (int j = 0; j < 4; j++) s[nt][j] = 0.f;
#pragma unroll
        for (int ks = 0; ks < 10; ks++) {
#pragma unroll
            for (int np = 0; np < 2; np++) {
                uint32_t kb[4];
                ldsm4_b2(kb, sK_u + (uint32_t)(buf * 10752),
                         np * 16, 336, ks * 32, lane);
                mmaf16(s[np * 2],     qa[ks], kb);
                mmaf16(s[np * 2 + 1], qa[ks], kb + 2);
            }
        }

        // ---- warp-local online softmax (rows g and g+8) ----
        float mx0 = fmaxf(fmaxf(s[0][0], s[0][1]), fmaxf(s[1][0], s[1][1]));
        mx0 = fmaxf(mx0, fmaxf(fmaxf(s[2][0], s[2][1]), fmaxf(s[3][0], s[3][1])));
        float mx1 = fmaxf(fmaxf(s[0][2], s[0][3]), fmaxf(s[1][2], s[1][3]));
        mx1 = fmaxf(mx1, fmaxf(fmaxf(s[2][2], s[2][3]), fmaxf(s[3][2], s[3][3])));
        mx0 = fmaxf(mx0, __shfl_xor_sync(0xffffffffu, mx0, 1));
        mx0 = fmaxf(mx0, __shfl_xor_sync(0xffffffffu, mx0, 2));
        mx1 = fmaxf(mx1, __shfl_xor_sync(0xffffffffu, mx1, 1));
        mx1 = fmaxf(mx1, __shfl_xor_sync(0xffffffffu, mx1, 2));

        float mn0 = fmaxf(m0, mx0), mn1 = fmaxf(m1, mx1);
        float a0 = fast_exp(m0 - mn0), a1 = fast_exp(m1 - mn1);
        m0 = mn0; m1 = mn1;

        float p[4][4];
        float sum0 = 0.f, sum1 = 0.f;
#pragma unroll
        for (int nt = 0; nt < 4; nt++) {
            p[nt][0] = fast_exp(s[nt][0] - mn0);
            p[nt][1] = fast_exp(s[nt][1] - mn0);
            p[nt][2] = fast_exp(s[nt][2] - mn1);
            p[nt][3] = fast_exp(s[nt][3] - mn1);
            sum0 += p[nt][0] + p[nt][1];
            sum1 += p[nt][2] + p[nt][3];
        }
        sum0 += __shfl_xor_sync(0xffffffffu, sum0, 1);
        sum0 += __shfl_xor_sync(0xffffffffu, sum0, 2);
        sum1 += __shfl_xor_sync(0xffffffffu, sum1, 1);
        sum1 += __shfl_xor_sync(0xffffffffu, sum1, 2);
        l0 = l0 * a0 + sum0;
        l1 = l1 * a1 + sum1;

        // ---- P accum regs -> fp16 A-frags (layout matches exactly) ----
        uint32_t pa[2][4];
#pragma unroll
        for (int j2 = 0; j2 < 2; j2++) {
            pa[j2][0] = f2h2(p[2 * j2][0],     p[2 * j2][1]);
            pa[j2][1] = f2h2(p[2 * j2][2],     p[2 * j2][3]);
            pa[j2][2] = f2h2(p[2 * j2 + 1][0], p[2 * j2 + 1][1]);
            pa[j2][3] = f2h2(p[2 * j2 + 1][2], p[2 * j2 + 1][3]);
        }

        // ---- rescale O, then O += P @ V ----
#pragma unroll
        for (int nt = 0; nt < 20; nt++) {
            o[nt][0] *= a0; o[nt][1] *= a0;
            o[nt][2] *= a1; o[nt][3] *= a1;
        }
#pragma unroll
        for (int j2 = 0; j2 < 2; j2++) {
#pragma unroll
            for (int np = 0; np < 10; np++) {
                uint32_t vb[4];
                ldsm4_b2(vb, sV_u + (uint32_t)(buf * 12800),
                         np * 16, 80, j2 * 32, lane);
                mmaf16(o[np * 2],     pa[j2], vb);
                mmaf16(o[np * 2 + 1], pa[j2], vb + 2);
            }
        }
    }

    // ---- epilogue: O / l -> g_aoh [row][1280] fp16 ----
    const int b = bh >> 3, h = bh & 7;
    float inv0 = 1.0f / l0, inv1 = 1.0f / l1;
    size_t ro0 = (size_t)(b * SEQ + r0) * CHN + h * HDIM;
    size_t ro1 = (size_t)(b * SEQ + r0 + 8) * CHN + h * HDIM;
#pragma unroll
    for (int nt = 0; nt < 20; nt++) {
        int d = nt * 8 + 2 * t;
        *(uint32_t*)&g_aoh[ro0 + d] = f2h2(o[nt][0] * inv0, o[nt][1] * inv0);
        *(uint32_t*)&g_aoh[ro1 + d] = f2h2(o[nt][2] * inv1, o[nt][3] * inv1);
    }
}

// ---------------------------------------------------------------------------
// Kernel 3: output projection + bias (fp16 HMMA, f32 out)
// ---------------------------------------------------------------------------
__global__ __launch_bounds__(256, 2) void out_h(
    const float* __restrict__ bias, float* __restrict__ out)
{
    extern __shared__ __half smem_g[];
    uint32_t smem_u = (uint32_t)__cvta_generic_to_shared(smem_g);
    float c[16][4];
#pragma unroll
    for (int i = 0; i < 16; i++)
#pragma unroll
        for (int j = 0; j < 4; j++) c[i][j] = 0.f;

    hgemm_core(g_aoh, g_woh, blockIdx.y * 128, blockIdx.x * 128, c, smem_u);

    const int lane = threadIdx.x & 31, warp = threadIdx.x >> 5;
    const int g = lane >> 2, t = lane & 3;
    const int wm = warp >> 2, wn = warp & 3;

#pragma unroll
    for (int mt = 0; mt < 4; mt++) {
#pragma unroll
        for (int nt = 0; nt < 4; nt++) {
            int r = blockIdx.y * 128 + wm * 64 + mt * 16 + g;
            int col = blockIdx.x * 128 + wn * 32 + nt * 8 + 2 * t;
            float2 bv = *(const float2*)&bias[col];
            float* cc = c[mt * 4 + nt];
#pragma unroll
            for (int hf = 0; hf < 2; hf++) {
                int row = r + hf * 8;
                *(float2*)&out[(size_t)row * CHN + col] =
                    make_float2(cc[hf * 2] + bv.x, cc[hf * 2 + 1] + bv.y);
            }
        }
    }
}

// ---------------------------------------------------------------------------
extern "C" void kernel_launch(void* const* d_in, const int* in_sizes, int n_in,
                              void* d_out, int out_size)
{
    const float* X    = (const float*)d_in[0];
    const float* Wq   = (const float*)d_in[1];
    const float* Wk   = (const float*)d_in[2];
    const float* Wv   = (const float*)d_in[3];
    const float* Wout = (const float*)d_in[4];
    const float* bout = (const float*)d_in[5];
    float* out = (float*)d_out;

    const int NX = MTOT * CHN / 4, NW = CHN * CHN / 4;
    cvt_all<<<(NX + 4 * NW + 255) / 256, 256>>>(X, Wq, Wk, Wv, Wout);

    cudaFuncSetAttribute(qkv_h,
                         cudaFuncAttributeMaxDynamicSharedMemorySize, GEMM_SMEM);
    qkv_h<<<dim3(CHN / 128, MTOT / 128, 3), 256, GEMM_SMEM>>>();

    cudaFuncSetAttribute(attn_h,
                         cudaFuncAttributeMaxDynamicSharedMemorySize, ATTN_SMEM);
    attn_h<<<dim3(SEQ / 128, BHN), 256, ATTN_SMEM>>>();

    cudaFuncSetAttribute(out_h,
                         cudaFuncAttributeMaxDynamicSharedMemorySize, GEMM_SMEM);
    out_h<<<dim3(CHN / 128, MTOT / 128), 256, GEMM_SMEM>>>(bout, out);
}